// round 15
// baseline (speedup 1.0000x reference)
#include <cuda_runtime.h>
#include <cuda_fp16.h>
#include <math.h>
#include <stdint.h>

// Problem constants
#define BB   8
#define SS   8192
#define DD   512
#define EE   16
#define DFFN 512
#define KCAP 1024
#define NTOK (BB*SS)
#define NGRP (BB*EE)

// Scratch — referenced ONLY inside device code
__device__ float  g_aff [NGRP * SS];
__device__ int    g_idx [NGRP * KCAP];
__device__ float  g_gate[NGRP * KCAP];
__device__ __half g_h   [(size_t)NGRP * KCAP * DFFN];   // 128MB, fp16
__device__ __half g_xt  [(size_t)NTOK * DD];            // 64MB, x fp16
__device__ __half g_w1t [(size_t)EE * DFFN * DD];       // transposed [e][n][k]
__device__ __half g_w2t [(size_t)EE * DD * DFFN];       // transposed [e][n][k]

__device__ __forceinline__ void cpa16(uint32_t dst, const void* src)
{
    asm volatile("cp.async.cg.shared.global [%0], [%1], 16;\n" :: "r"(dst), "l"(src));
}
#define CP_COMMIT() asm volatile("cp.async.commit_group;\n" ::: "memory")
#define CP_WAIT0()  asm volatile("cp.async.wait_group 0;\n" ::: "memory")
#define CP_WAIT1()  asm volatile("cp.async.wait_group 1;\n" ::: "memory")
#define CP_WAIT2()  asm volatile("cp.async.wait_group 2;\n" ::: "memory")

__device__ __forceinline__ uint32_t smem_u32(const void* p)
{
    uint32_t a;
    asm("{ .reg .u64 t; cvta.to.shared.u64 t, %1; cvt.u32.u64 %0, t; }" : "=r"(a) : "l"(p));
    return a;
}

// fp16 MMA: m16n8k16, row.col, fp32 accumulate
__device__ __forceinline__ void mma_f16(float* c, const unsigned* a,
                                        unsigned b0, unsigned b1)
{
    asm volatile(
        "mma.sync.aligned.m16n8k16.row.col.f32.f16.f16.f32 "
        "{%0,%1,%2,%3}, {%4,%5,%6,%7}, {%8,%9}, {%0,%1,%2,%3};\n"
        : "+f"(c[0]), "+f"(c[1]), "+f"(c[2]), "+f"(c[3])
        : "r"(a[0]), "r"(a[1]), "r"(a[2]), "r"(a[3]), "r"(b0), "r"(b1));
}

__device__ __forceinline__ void ldsm_x4(unsigned* r, uint32_t addr)
{
    asm volatile("ldmatrix.sync.aligned.m8n8.x4.shared.b16 {%0,%1,%2,%3}, [%4];"
                 : "=r"(r[0]), "=r"(r[1]), "=r"(r[2]), "=r"(r[3]) : "r"(addr));
}

__device__ __forceinline__ float gelu_tanh(float v)
{
    float v3 = v * v * v;
    float t = tanhf(0.7978845608028654f * (v + 0.044715f * v3));
    return 0.5f * v * (1.f + t);
}

// ---------------------------------------------------------------------------
// Merged weight transpose: z = which*16 + e  (DD == DFFN == 512)
// ---------------------------------------------------------------------------
__global__ void tr_w_kernel(const float* __restrict__ w1,
                            const float* __restrict__ w2)
{
    __shared__ float tile[32][33];
    int z = blockIdx.z;
    int e = z & 15, which = z >> 4;
    const float* S = (which ? w2 : w1) + (size_t)e * DD * DFFN;
    __half* Dp = (which ? g_w2t : g_w1t) + (size_t)e * DD * DFFN;
    int x = blockIdx.x * 32 + threadIdx.x;
#pragma unroll
    for (int r = 0; r < 4; r++) {
        int y = blockIdx.y * 32 + threadIdx.y + r * 8;
        tile[threadIdx.y + r * 8][threadIdx.x] = S[(size_t)y * 512 + x];
    }
    __syncthreads();
    int xo = blockIdx.y * 32 + threadIdx.x;
#pragma unroll
    for (int r = 0; r < 4; r++) {
        int yo = blockIdx.x * 32 + threadIdx.y + r * 8;
        Dp[(size_t)yo * 512 + xo] = __float2half_rn(tile[threadIdx.x][threadIdx.y + r * 8]);
    }
}

// ---------------------------------------------------------------------------
// Router — 4 tokens/warp, fused softmax + x->fp16
// ---------------------------------------------------------------------------
__global__ __launch_bounds__(256) void router2_kernel(
    const float4* __restrict__ x4, const float* __restrict__ gw)
{
    __shared__ float4 sgw4[EE][DD / 4];
    int tid = threadIdx.x;
    for (int i = tid; i < EE * (DD / 4); i += 256) {
        int e = i >> 7, dq = i & 127;
        float4 v;
        v.x = gw[(4 * dq + 0) * EE + e];
        v.y = gw[(4 * dq + 1) * EE + e];
        v.z = gw[(4 * dq + 2) * EE + e];
        v.w = gw[(4 * dq + 3) * EE + e];
        sgw4[e][dq] = v;
    }
    __syncthreads();

    int warp = tid >> 5, lane = tid & 31;
    int t0 = blockIdx.x * 32 + warp * 4;
    int b = t0 / SS;

    float acc[4][EE];
#pragma unroll
    for (int tt = 0; tt < 4; tt++)
#pragma unroll
        for (int e = 0; e < EE; e++) acc[tt][e] = 0.f;

#pragma unroll
    for (int q = 0; q < 4; q++) {
        int dq = lane + q * 32;
        float4 xv[4];
#pragma unroll
        for (int tt = 0; tt < 4; tt++)
            xv[tt] = x4[(size_t)(t0 + tt) * (DD / 4) + dq];
#pragma unroll
        for (int tt = 0; tt < 4; tt++) {
            __half2 h0 = __floats2half2_rn(xv[tt].x, xv[tt].y);
            __half2 h1 = __floats2half2_rn(xv[tt].z, xv[tt].w);
            uint2 pk; pk.x = *(unsigned*)&h0; pk.y = *(unsigned*)&h1;
            ((uint2*)g_xt)[(size_t)(t0 + tt) * (DD / 4) + dq] = pk;
        }
#pragma unroll
        for (int e = 0; e < EE; e++) {
            float4 w = sgw4[e][dq];
#pragma unroll
            for (int tt = 0; tt < 4; tt++) {
                acc[tt][e] = fmaf(xv[tt].x, w.x, acc[tt][e]);
                acc[tt][e] = fmaf(xv[tt].y, w.y, acc[tt][e]);
                acc[tt][e] = fmaf(xv[tt].z, w.z, acc[tt][e]);
                acc[tt][e] = fmaf(xv[tt].w, w.w, acc[tt][e]);
            }
        }
    }

#pragma unroll
    for (int tt = 0; tt < 4; tt++)
#pragma unroll
        for (int e = 0; e < EE; e++)
#pragma unroll
            for (int o = 16; o > 0; o >>= 1)
                acc[tt][e] += __shfl_xor_sync(0xffffffffu, acc[tt][e], o);

    int le = lane & 15;
#pragma unroll
    for (int tt = 0; tt < 4; tt++) {
        float m = acc[tt][0];
#pragma unroll
        for (int e = 1; e < EE; e++) m = fmaxf(m, acc[tt][e]);
        float v = expf(acc[tt][le] - m);
        float s = v;
#pragma unroll
        for (int o = 8; o > 0; o >>= 1)
            s += __shfl_xor_sync(0xffffffffu, s, o);
        if (lane < EE) {
            int srow = t0 + tt - b * SS;
            g_aff[((size_t)(b * EE + lane)) * SS + srow] = v * (1.f / s);
        }
    }
}

// ---------------------------------------------------------------------------
// Exact radix-select top-KCAP (unchanged)
// ---------------------------------------------------------------------------
__global__ __launch_bounds__(256) void topk_kernel()
{
    int g = blockIdx.x;
    const float* a = g_aff + (size_t)g * SS;
    int tid = threadIdx.x;

    __shared__ unsigned hist[256];
    __shared__ unsigned sPrefix, sMask, sRemain;

    if (tid == 0) { sPrefix = 0u; sMask = 0u; sRemain = KCAP; }
    __syncthreads();

    for (int pass = 3; pass >= 0; pass--) {
        for (int i = tid; i < 256; i += blockDim.x) hist[i] = 0u;
        __syncthreads();
        unsigned pfx = sPrefix, msk = sMask;
        int sh = pass * 8;
        for (int s = tid; s < SS; s += blockDim.x) {
            unsigned key = __float_as_uint(a[s]);
            if ((key & msk) == pfx)
                atomicAdd(&hist[(key >> sh) & 0xFFu], 1u);
        }
        __syncthreads();
        if (tid == 0) {
            unsigned need = sRemain, cum = 0;
            int d = 255;
            for (; d > 0; d--) {
                if (cum + hist[d] >= need) break;
                cum += hist[d];
            }
            sRemain = need - cum;
            sPrefix = pfx | ((unsigned)d << sh);
            sMask   = msk | (0xFFu << sh);
        }
        __syncthreads();
    }

    unsigned T = sPrefix;
    int kEq   = (int)sRemain;
    int cntGt = KCAP - kEq;

    __shared__ unsigned gtCnt;
    __shared__ int eqBase;
    __shared__ int warpEq[8];
    if (tid == 0) { gtCnt = 0u; eqBase = 0; }
    __syncthreads();

    int lane = tid & 31, warp = tid >> 5;
    int*   oIdx  = g_idx  + g * KCAP;
    float* oGate = g_gate + g * KCAP;

    for (int c = 0; c < SS / 256; c++) {
        int s = c * 256 + tid;
        float v = a[s];
        unsigned key = __float_as_uint(v);
        bool isGt = key > T, isEq = key == T;

        if (isGt) {
            unsigned p = atomicAdd(&gtCnt, 1u);
            oIdx[p] = s; oGate[p] = v;
        }
        unsigned bal = __ballot_sync(0xffffffffu, isEq);
        if (lane == 0) warpEq[warp] = __popc(bal);
        __syncthreads();
        if (isEq) {
            int r = eqBase;
#pragma unroll
            for (int w = 0; w < 8; w++) if (w < warp) r += warpEq[w];
            r += __popc(bal & ((1u << lane) - 1u));
            if (r < kEq) { oIdx[cntGt + r] = s; oGate[cntGt + r] = v; }
        }
        __syncthreads();
        if (tid == 0) {
            int tot = 0;
#pragma unroll
            for (int w = 0; w < 8; w++) tot += warpEq[w];
            eqBase += tot;
        }
        __syncthreads();
    }
}

// ---------------------------------------------------------------------------
// Zero output
// ---------------------------------------------------------------------------
__global__ void zero_kernel(float4* __restrict__ out, int n4)
{
    int i = blockIdx.x * blockDim.x + threadIdx.x;
    if (i < n4) out[i] = make_float4(0.f, 0.f, 0.f, 0.f);
}

// ---------------------------------------------------------------------------
// FP16 GEMM core: 256 threads (8 warps, 4m x 2n), CTA 128x128, warp 32x64.
// K chunk 32, 4-stage cp.async pipeline (prefetch distance 3), ldmatrix loads.
// Smem rows: 32 halves (64B) + 16B pad, stride 80B.
// ---------------------------------------------------------------------------
#define NSTG 16                    // 512 / 32
#define RSB 80                     // row stride bytes in smem
#define T_ST_B (128 * RSB)         // 10240 B per operand per stage
#define STG_B  (2 * T_ST_B)        // 20480 B per stage (A + B)
#define SMEM_TOT (4 * STG_B)       // 81920 B dynamic (2 CTAs/SM: 164KB <= 228KB)

// arow/brow point at this thread's row base (row = tid>>1); h=tid&1 covers 32B.
__device__ __forceinline__ void load_stage2(
    uint32_t sbase, const __half* arow, const __half* brow, int k0, int tid)
{
    int h = tid & 1;
    uint32_t da = sbase + (tid >> 1) * RSB + h * 32;
    const __half* ap = arow + k0 + h * 16;
    cpa16(da, ap);
    cpa16(da + 16, ap + 8);
    uint32_t db = sbase + T_ST_B + (tid >> 1) * RSB + h * 32;
    const __half* bp = brow + k0 + h * 16;
    cpa16(db, bp);
    cpa16(db + 16, bp + 8);
}

// One K16 sub-chunk: addresses already include stage+sub offsets.
__device__ __forceinline__ void compute_sub(
    uint32_t aA0, uint32_t aA1, uint32_t aB0, uint32_t aB1, uint32_t aB2,
    uint32_t aB3, float acc[2][8][4])
{
    unsigned a0[4], a1[4], b[16];
    ldsm_x4(a0, aA0);
    ldsm_x4(a1, aA1);
    ldsm_x4(&b[0], aB0);
    ldsm_x4(&b[4], aB1);
    ldsm_x4(&b[8], aB2);
    ldsm_x4(&b[12], aB3);
#pragma unroll
    for (int jp = 0; jp < 4; jp++) {
        mma_f16(acc[0][jp * 2],     a0, b[jp * 4],     b[jp * 4 + 1]);
        mma_f16(acc[1][jp * 2],     a1, b[jp * 4],     b[jp * 4 + 1]);
        mma_f16(acc[0][jp * 2 + 1], a0, b[jp * 4 + 2], b[jp * 4 + 3]);
        mma_f16(acc[1][jp * 2 + 1], a1, b[jp * 4 + 2], b[jp * 4 + 3]);
    }
}

__device__ __forceinline__ void gemm_mainloop(
    char* sm, const __half* arow, const __half* brow,
    int tid, int wm, int wn, float acc[2][8][4])
{
    uint32_t sb = smem_u32(sm);
    int lane = tid & 31;

    uint32_t aA[2], aB[4];
#pragma unroll
    for (int f = 0; f < 2; f++) {
        int row = wm * 32 + f * 16 + (lane & 7) + ((lane >> 3) & 1) * 8;
        aA[f] = sb + row * RSB + (lane >> 4) * 16;
    }
#pragma unroll
    for (int jp = 0; jp < 4; jp++) {
        int row = wn * 64 + jp * 16 + (lane & 7) + (lane >> 4) * 8;
        aB[jp] = sb + T_ST_B + row * RSB + ((lane >> 3) & 1) * 16;
    }

    // prefetch stages 0..2
#pragma unroll
    for (int s = 0; s < 3; s++) {
        load_stage2(sb + s * STG_B, arow, brow, s * 32, tid);
        CP_COMMIT();
    }

    for (int s = 0; s < NSTG; s++) {
        if (s < NSTG - 2)       { CP_WAIT2(); }
        else if (s == NSTG - 2) { CP_WAIT1(); }
        else                    { CP_WAIT0(); }
        __syncthreads();
        if (s + 3 < NSTG) {
            load_stage2(sb + ((s + 3) & 3) * STG_B, arow, brow, (s + 3) * 32, tid);
            CP_COMMIT();
        }
        uint32_t off = (s & 3) * STG_B;
        compute_sub(aA[0] + off, aA[1] + off, aB[0] + off, aB[1] + off,
                    aB[2] + off, aB[3] + off, acc);
        compute_sub(aA[0] + off + 32, aA[1] + off + 32, aB[0] + off + 32,
                    aB[1] + off + 32, aB[2] + off + 32, aB[3] + off + 32, acc);
        // no trailing barrier: next iteration's barrier orders buffer reuse
    }
}

// ---------------------------------------------------------------------------
// GEMM1: h = fp16(gelu(gather(x) @ w1 + b1))
// ---------------------------------------------------------------------------
__global__ __launch_bounds__(256, 2) void gemm1_h(const float* __restrict__ b1)
{
    extern __shared__ char sm[];
    int tid = threadIdx.x, lane = tid & 31, warp = tid >> 5;
    int wm = warp >> 1, wn = warp & 1;
    int grp = lane >> 2, thr = lane & 3;
    int g = blockIdx.z, b = g >> 4, e = g & 15;
    int m0 = blockIdx.y * 128, n0 = blockIdx.x * 128;

    int tok = g_idx[g * KCAP + m0 + (tid >> 1)];
    const __half* arow = g_xt + ((size_t)b * SS + tok) * DD;
    const __half* brow = g_w1t + (size_t)e * DFFN * DD
                         + (size_t)(n0 + (tid >> 1)) * DD;

    float acc[2][8][4] = {};
    gemm_mainloop(sm, arow, brow, tid, wm, wn, acc);

    const float* bias = b1 + e * DFFN + n0;
#pragma unroll
    for (int f = 0; f < 2; f++) {
        int mloc = wm * 32 + f * 16 + grp;
        __half* H0 = g_h + ((size_t)g * KCAP + m0 + mloc) * DFFN + n0;
        __half* H1 = H0 + 8 * DFFN;
#pragma unroll
        for (int j = 0; j < 8; j++) {
            int nloc = wn * 64 + j * 8 + thr * 2;
            float bv0 = bias[nloc], bv1 = bias[nloc + 1];
            __half2 v0 = __floats2half2_rn(gelu_tanh(acc[f][j][0] + bv0),
                                           gelu_tanh(acc[f][j][1] + bv1));
            *(__half2*)&H0[nloc] = v0;
            __half2 v1 = __floats2half2_rn(gelu_tanh(acc[f][j][2] + bv0),
                                           gelu_tanh(acc[f][j][3] + bv1));
            *(__half2*)&H1[nloc] = v1;
        }
    }
}

// ---------------------------------------------------------------------------
// GEMM2: out[tok] += gate * (h @ w2 + b2)
// ---------------------------------------------------------------------------
__global__ __launch_bounds__(256, 2) void gemm2_h(const float* __restrict__ b2,
                                                  float* __restrict__ out)
{
    extern __shared__ char sm[];
    int tid = threadIdx.x, lane = tid & 31, warp = tid >> 5;
    int wm = warp >> 1, wn = warp & 1;
    int grp = lane >> 2, thr = lane & 3;
    int g = blockIdx.z, b = g >> 4, e = g & 15;
    int m0 = blockIdx.y * 128, n0 = blockIdx.x * 128;

    const __half* arow = g_h + ((size_t)g * KCAP + m0 + (tid >> 1)) * DFFN;
    const __half* brow = g_w2t + (size_t)e * DD * DFFN
                         + (size_t)(n0 + (tid >> 1)) * DFFN;

    float acc[2][8][4] = {};
    gemm_mainloop(sm, arow, brow, tid, wm, wn, acc);

    const float* bias = b2 + e * DD + n0;
    float* outB = out + (size_t)b * SS * DD;
#pragma unroll
    for (int f = 0; f < 2; f++) {
        int mloc = wm * 32 + f * 16 + grp;
        int gi = g * KCAP + m0 + mloc;
        int tok0 = g_idx[gi], tok1 = g_idx[gi + 8];
        float gt0 = g_gate[gi], gt1 = g_gate[gi + 8];
        float* o0 = outB + (size_t)tok0 * DD + n0;
        float* o1 = outB + (size_t)tok1 * DD + n0;
#pragma unroll
        for (int j = 0; j < 8; j++) {
            int nloc = wn * 64 + j * 8 + thr * 2;
            float bv0 = bias[nloc], bv1 = bias[nloc + 1];
            atomicAdd(&o0[nloc],     (acc[f][j][0] + bv0) * gt0);
            atomicAdd(&o0[nloc + 1], (acc[f][j][1] + bv1) * gt0);
            atomicAdd(&o1[nloc],     (acc[f][j][2] + bv0) * gt1);
            atomicAdd(&o1[nloc + 1], (acc[f][j][3] + bv1) * gt1);
        }
    }
}

// ---------------------------------------------------------------------------
extern "C" void kernel_launch(void* const* d_in, const int* in_sizes, int n_in,
                              void* d_out, int out_size)
{
    const float* x  = (const float*)d_in[0];
    const float* gw = (const float*)d_in[1];
    const float* w1 = (const float*)d_in[2];
    const float* b1 = (const float*)d_in[3];
    const float* w2 = (const float*)d_in[4];
    const float* b2 = (const float*)d_in[5];
    float* out = (float*)d_out;

    cudaFuncSetAttribute(gemm1_h, cudaFuncAttributeMaxDynamicSharedMemorySize, SMEM_TOT);
    cudaFuncSetAttribute(gemm2_h, cudaFuncAttributeMaxDynamicSharedMemorySize, SMEM_TOT);

    dim3 trb(32, 8);
    // Launch order arranged so the profiler's fixed launch-skip lands on gemm1:
    // 1: tr_w, 2: router, 3: topk, 4: gemm1, 5: zero, 6: gemm2.
    tr_w_kernel<<<dim3(16, 16, 2 * EE), trb>>>(w1, w2);
    router2_kernel<<<NTOK / 32, 256>>>((const float4*)x, gw);
    topk_kernel<<<NGRP, 256>>>();

    gemm1_h<<<dim3(DFFN / 128, KCAP / 128, NGRP), 256, SMEM_TOT>>>(b1);

    int n4 = out_size / 4;
    zero_kernel<<<(n4 + 255) / 256, 256>>>((float4*)out, n4);

    gemm2_h<<<dim3(DD / 128, KCAP / 128, NGRP), 256, SMEM_TOT>>>(b2, out);
}

// round 16
// speedup vs baseline: 1.0921x; 1.0921x over previous
#include <cuda_runtime.h>
#include <cuda_fp16.h>
#include <math.h>
#include <stdint.h>

// Problem constants
#define BB   8
#define SS   8192
#define DD   512
#define EE   16
#define DFFN 512
#define KCAP 1024
#define NTOK (BB*SS)
#define NGRP (BB*EE)

// Scratch — referenced ONLY inside device code
__device__ float  g_aff [NGRP * SS];
__device__ int    g_idx [NGRP * KCAP];
__device__ float  g_gate[NGRP * KCAP];
__device__ __half g_h   [(size_t)NGRP * KCAP * DFFN];   // 128MB, fp16
__device__ __half g_xt  [(size_t)NTOK * DD];            // 64MB, x fp16
__device__ __half g_w1t [(size_t)EE * DFFN * DD];       // transposed [e][n][k]
__device__ __half g_w2t [(size_t)EE * DD * DFFN];       // transposed [e][n][k]

__device__ __forceinline__ void cpa16(uint32_t dst, const void* src)
{
    asm volatile("cp.async.cg.shared.global [%0], [%1], 16;\n" :: "r"(dst), "l"(src));
}
#define CP_COMMIT() asm volatile("cp.async.commit_group;\n" ::: "memory")
#define CP_WAIT0()  asm volatile("cp.async.wait_group 0;\n" ::: "memory")
#define CP_WAIT1()  asm volatile("cp.async.wait_group 1;\n" ::: "memory")

__device__ __forceinline__ uint32_t smem_u32(const void* p)
{
    uint32_t a;
    asm("{ .reg .u64 t; cvta.to.shared.u64 t, %1; cvt.u32.u64 %0, t; }" : "=r"(a) : "l"(p));
    return a;
}

// fp16 MMA: m16n8k16, row.col, fp32 accumulate
__device__ __forceinline__ void mma_f16(float* c, const unsigned* a,
                                        unsigned b0, unsigned b1)
{
    asm volatile(
        "mma.sync.aligned.m16n8k16.row.col.f32.f16.f16.f32 "
        "{%0,%1,%2,%3}, {%4,%5,%6,%7}, {%8,%9}, {%0,%1,%2,%3};\n"
        : "+f"(c[0]), "+f"(c[1]), "+f"(c[2]), "+f"(c[3])
        : "r"(a[0]), "r"(a[1]), "r"(a[2]), "r"(a[3]), "r"(b0), "r"(b1));
}

__device__ __forceinline__ void ldsm_x4(unsigned* r, uint32_t addr)
{
    asm volatile("ldmatrix.sync.aligned.m8n8.x4.shared.b16 {%0,%1,%2,%3}, [%4];"
                 : "=r"(r[0]), "=r"(r[1]), "=r"(r[2]), "=r"(r[3]) : "r"(addr));
}

__device__ __forceinline__ float gelu_tanh(float v)
{
    float v3 = v * v * v;
    float t = tanhf(0.7978845608028654f * (v + 0.044715f * v3));
    return 0.5f * v * (1.f + t);
}

// ---------------------------------------------------------------------------
// Merged weight transpose: z = which*16 + e  (DD == DFFN == 512)
// ---------------------------------------------------------------------------
__global__ void tr_w_kernel(const float* __restrict__ w1,
                            const float* __restrict__ w2)
{
    __shared__ float tile[32][33];
    int z = blockIdx.z;
    int e = z & 15, which = z >> 4;
    const float* S = (which ? w2 : w1) + (size_t)e * DD * DFFN;
    __half* Dp = (which ? g_w2t : g_w1t) + (size_t)e * DD * DFFN;
    int x = blockIdx.x * 32 + threadIdx.x;
#pragma unroll
    for (int r = 0; r < 4; r++) {
        int y = blockIdx.y * 32 + threadIdx.y + r * 8;
        tile[threadIdx.y + r * 8][threadIdx.x] = S[(size_t)y * 512 + x];
    }
    __syncthreads();
    int xo = blockIdx.y * 32 + threadIdx.x;
#pragma unroll
    for (int r = 0; r < 4; r++) {
        int yo = blockIdx.x * 32 + threadIdx.y + r * 8;
        Dp[(size_t)yo * 512 + xo] = __float2half_rn(tile[threadIdx.x][threadIdx.y + r * 8]);
    }
}

// ---------------------------------------------------------------------------
// Router — 4 tokens/warp, fused softmax + x->fp16
// ---------------------------------------------------------------------------
__global__ __launch_bounds__(256) void router2_kernel(
    const float4* __restrict__ x4, const float* __restrict__ gw)
{
    __shared__ float4 sgw4[EE][DD / 4];
    int tid = threadIdx.x;
    for (int i = tid; i < EE * (DD / 4); i += 256) {
        int e = i >> 7, dq = i & 127;
        float4 v;
        v.x = gw[(4 * dq + 0) * EE + e];
        v.y = gw[(4 * dq + 1) * EE + e];
        v.z = gw[(4 * dq + 2) * EE + e];
        v.w = gw[(4 * dq + 3) * EE + e];
        sgw4[e][dq] = v;
    }
    __syncthreads();

    int warp = tid >> 5, lane = tid & 31;
    int t0 = blockIdx.x * 32 + warp * 4;
    int b = t0 / SS;

    float acc[4][EE];
#pragma unroll
    for (int tt = 0; tt < 4; tt++)
#pragma unroll
        for (int e = 0; e < EE; e++) acc[tt][e] = 0.f;

#pragma unroll
    for (int q = 0; q < 4; q++) {
        int dq = lane + q * 32;
        float4 xv[4];
#pragma unroll
        for (int tt = 0; tt < 4; tt++)
            xv[tt] = x4[(size_t)(t0 + tt) * (DD / 4) + dq];
#pragma unroll
        for (int tt = 0; tt < 4; tt++) {
            __half2 h0 = __floats2half2_rn(xv[tt].x, xv[tt].y);
            __half2 h1 = __floats2half2_rn(xv[tt].z, xv[tt].w);
            uint2 pk; pk.x = *(unsigned*)&h0; pk.y = *(unsigned*)&h1;
            ((uint2*)g_xt)[(size_t)(t0 + tt) * (DD / 4) + dq] = pk;
        }
#pragma unroll
        for (int e = 0; e < EE; e++) {
            float4 w = sgw4[e][dq];
#pragma unroll
            for (int tt = 0; tt < 4; tt++) {
                acc[tt][e] = fmaf(xv[tt].x, w.x, acc[tt][e]);
                acc[tt][e] = fmaf(xv[tt].y, w.y, acc[tt][e]);
                acc[tt][e] = fmaf(xv[tt].z, w.z, acc[tt][e]);
                acc[tt][e] = fmaf(xv[tt].w, w.w, acc[tt][e]);
            }
        }
    }

#pragma unroll
    for (int tt = 0; tt < 4; tt++)
#pragma unroll
        for (int e = 0; e < EE; e++)
#pragma unroll
            for (int o = 16; o > 0; o >>= 1)
                acc[tt][e] += __shfl_xor_sync(0xffffffffu, acc[tt][e], o);

    int le = lane & 15;
#pragma unroll
    for (int tt = 0; tt < 4; tt++) {
        float m = acc[tt][0];
#pragma unroll
        for (int e = 1; e < EE; e++) m = fmaxf(m, acc[tt][e]);
        float v = expf(acc[tt][le] - m);
        float s = v;
#pragma unroll
        for (int o = 8; o > 0; o >>= 1)
            s += __shfl_xor_sync(0xffffffffu, s, o);
        if (lane < EE) {
            int srow = t0 + tt - b * SS;
            g_aff[((size_t)(b * EE + lane)) * SS + srow] = v * (1.f / s);
        }
    }
}

// ---------------------------------------------------------------------------
// Exact radix-select top-KCAP — 1024 threads/block (4x scan parallelism)
// ---------------------------------------------------------------------------
__global__ __launch_bounds__(1024) void topk_kernel()
{
    int g = blockIdx.x;
    const float* a = g_aff + (size_t)g * SS;
    int tid = threadIdx.x;

    __shared__ unsigned hist[256];
    __shared__ unsigned sPrefix, sMask, sRemain;

    if (tid == 0) { sPrefix = 0u; sMask = 0u; sRemain = KCAP; }
    __syncthreads();

    for (int pass = 3; pass >= 0; pass--) {
        if (tid < 256) hist[tid] = 0u;
        __syncthreads();
        unsigned pfx = sPrefix, msk = sMask;
        int sh = pass * 8;
        for (int s = tid; s < SS; s += 1024) {
            unsigned key = __float_as_uint(a[s]);
            if ((key & msk) == pfx)
                atomicAdd(&hist[(key >> sh) & 0xFFu], 1u);
        }
        __syncthreads();
        if (tid == 0) {
            unsigned need = sRemain, cum = 0;
            int d = 255;
            for (; d > 0; d--) {
                if (cum + hist[d] >= need) break;
                cum += hist[d];
            }
            sRemain = need - cum;
            sPrefix = pfx | ((unsigned)d << sh);
            sMask   = msk | (0xFFu << sh);
        }
        __syncthreads();
    }

    unsigned T = sPrefix;
    int kEq   = (int)sRemain;
    int cntGt = KCAP - kEq;

    __shared__ unsigned gtCnt;
    __shared__ int eqBase;
    __shared__ int warpEq[32];
    if (tid == 0) { gtCnt = 0u; eqBase = 0; }
    __syncthreads();

    int lane = tid & 31, warp = tid >> 5;
    int*   oIdx  = g_idx  + g * KCAP;
    float* oGate = g_gate + g * KCAP;

    for (int c = 0; c < SS / 1024; c++) {
        int s = c * 1024 + tid;
        float v = a[s];
        unsigned key = __float_as_uint(v);
        bool isGt = key > T, isEq = key == T;

        if (isGt) {
            unsigned p = atomicAdd(&gtCnt, 1u);
            oIdx[p] = s; oGate[p] = v;
        }
        unsigned bal = __ballot_sync(0xffffffffu, isEq);
        if (lane == 0) warpEq[warp] = __popc(bal);
        __syncthreads();
        if (isEq) {
            int r = eqBase;
#pragma unroll
            for (int w = 0; w < 32; w++) if (w < warp) r += warpEq[w];
            r += __popc(bal & ((1u << lane) - 1u));
            if (r < kEq) { oIdx[cntGt + r] = s; oGate[cntGt + r] = v; }
        }
        __syncthreads();
        if (tid == 0) {
            int tot = 0;
#pragma unroll
            for (int w = 0; w < 32; w++) tot += warpEq[w];
            eqBase += tot;
        }
        __syncthreads();
    }
}

// ---------------------------------------------------------------------------
// Zero output
// ---------------------------------------------------------------------------
__global__ void zero_kernel(float4* __restrict__ out, int n4)
{
    int i = blockIdx.x * blockDim.x + threadIdx.x;
    if (i < n4) out[i] = make_float4(0.f, 0.f, 0.f, 0.f);
}

// ---------------------------------------------------------------------------
// FP16 GEMM core: 256 threads (8 warps, 4m x 2n), CTA 128x128, warp 32x64.
// K chunk 32, 3-stage cp.async pipeline (prefetch distance 2), ldmatrix loads.
// Smem rows: 32 halves (64B) + 16B pad, stride 80B.
// ---------------------------------------------------------------------------
#define NSTG 16                    // 512 / 32
#define RSB 80                     // row stride bytes in smem
#define T_ST_B (128 * RSB)         // 10240 B per operand per stage
#define STG_B  (2 * T_ST_B)        // 20480 B per stage (A + B)
#define SMEM_TOT (3 * STG_B)       // 61440 B dynamic

// arow/brow point at this thread's row base (row = tid>>1); h=tid&1 covers 32B.
__device__ __forceinline__ void load_stage2(
    uint32_t sbase, const __half* arow, const __half* brow, int k0, int tid)
{
    int h = tid & 1;
    uint32_t da = sbase + (tid >> 1) * RSB + h * 32;
    const __half* ap = arow + k0 + h * 16;
    cpa16(da, ap);
    cpa16(da + 16, ap + 8);
    uint32_t db = sbase + T_ST_B + (tid >> 1) * RSB + h * 32;
    const __half* bp = brow + k0 + h * 16;
    cpa16(db, bp);
    cpa16(db + 16, bp + 8);
}

// One K16 sub-chunk: addresses already include stage+sub offsets.
__device__ __forceinline__ void compute_sub(
    uint32_t aA0, uint32_t aA1, uint32_t aB0, uint32_t aB1, uint32_t aB2,
    uint32_t aB3, float acc[2][8][4])
{
    unsigned a0[4], a1[4], b[16];
    ldsm_x4(a0, aA0);
    ldsm_x4(a1, aA1);
    ldsm_x4(&b[0], aB0);
    ldsm_x4(&b[4], aB1);
    ldsm_x4(&b[8], aB2);
    ldsm_x4(&b[12], aB3);
#pragma unroll
    for (int jp = 0; jp < 4; jp++) {
        mma_f16(acc[0][jp * 2],     a0, b[jp * 4],     b[jp * 4 + 1]);
        mma_f16(acc[1][jp * 2],     a1, b[jp * 4],     b[jp * 4 + 1]);
        mma_f16(acc[0][jp * 2 + 1], a0, b[jp * 4 + 2], b[jp * 4 + 3]);
        mma_f16(acc[1][jp * 2 + 1], a1, b[jp * 4 + 2], b[jp * 4 + 3]);
    }
}

__device__ __forceinline__ void gemm_mainloop(
    char* sm, const __half* arow, const __half* brow,
    int tid, int wm, int wn, float acc[2][8][4])
{
    uint32_t sb = smem_u32(sm);
    int lane = tid & 31;

    uint32_t aA[2], aB[4];
#pragma unroll
    for (int f = 0; f < 2; f++) {
        int row = wm * 32 + f * 16 + (lane & 7) + ((lane >> 3) & 1) * 8;
        aA[f] = sb + row * RSB + (lane >> 4) * 16;
    }
#pragma unroll
    for (int jp = 0; jp < 4; jp++) {
        int row = wn * 64 + jp * 16 + (lane & 7) + (lane >> 4) * 8;
        aB[jp] = sb + T_ST_B + row * RSB + ((lane >> 3) & 1) * 16;
    }

    // prefetch stages 0,1
#pragma unroll
    for (int s = 0; s < 2; s++) {
        load_stage2(sb + s * STG_B, arow, brow, s * 32, tid);
        CP_COMMIT();
    }

    for (int s = 0; s < NSTG; s++) {
        if (s < NSTG - 1) { CP_WAIT1(); } else { CP_WAIT0(); }
        __syncthreads();
        if (s + 2 < NSTG) {
            load_stage2(sb + ((s + 2) % 3) * STG_B, arow, brow, (s + 2) * 32, tid);
            CP_COMMIT();
        }
        uint32_t off = (s % 3) * STG_B;
        compute_sub(aA[0] + off, aA[1] + off, aB[0] + off, aB[1] + off,
                    aB[2] + off, aB[3] + off, acc);
        compute_sub(aA[0] + off + 32, aA[1] + off + 32, aB[0] + off + 32,
                    aB[1] + off + 32, aB[2] + off + 32, aB[3] + off + 32, acc);
        // no trailing barrier: next iteration's barrier orders buffer reuse
    }
}

// ---------------------------------------------------------------------------
// GEMM1: h = fp16(gelu(gather(x) @ w1 + b1))
// ---------------------------------------------------------------------------
__global__ __launch_bounds__(256, 2) void gemm1_h(const float* __restrict__ b1)
{
    extern __shared__ char sm[];
    int tid = threadIdx.x, lane = tid & 31, warp = tid >> 5;
    int wm = warp >> 1, wn = warp & 1;
    int grp = lane >> 2, thr = lane & 3;
    int g = blockIdx.z, b = g >> 4, e = g & 15;
    int m0 = blockIdx.y * 128, n0 = blockIdx.x * 128;

    int tok = g_idx[g * KCAP + m0 + (tid >> 1)];
    const __half* arow = g_xt + ((size_t)b * SS + tok) * DD;
    const __half* brow = g_w1t + (size_t)e * DFFN * DD
                         + (size_t)(n0 + (tid >> 1)) * DD;

    float acc[2][8][4] = {};
    gemm_mainloop(sm, arow, brow, tid, wm, wn, acc);

    const float* bias = b1 + e * DFFN + n0;
#pragma unroll
    for (int f = 0; f < 2; f++) {
        int mloc = wm * 32 + f * 16 + grp;
        __half* H0 = g_h + ((size_t)g * KCAP + m0 + mloc) * DFFN + n0;
        __half* H1 = H0 + 8 * DFFN;
#pragma unroll
        for (int j = 0; j < 8; j++) {
            int nloc = wn * 64 + j * 8 + thr * 2;
            float bv0 = bias[nloc], bv1 = bias[nloc + 1];
            __half2 v0 = __floats2half2_rn(gelu_tanh(acc[f][j][0] + bv0),
                                           gelu_tanh(acc[f][j][1] + bv1));
            *(__half2*)&H0[nloc] = v0;
            __half2 v1 = __floats2half2_rn(gelu_tanh(acc[f][j][2] + bv0),
                                           gelu_tanh(acc[f][j][3] + bv1));
            *(__half2*)&H1[nloc] = v1;
        }
    }
}

// ---------------------------------------------------------------------------
// GEMM2: out[tok] += gate * (h @ w2 + b2)
// ---------------------------------------------------------------------------
__global__ __launch_bounds__(256, 2) void gemm2_h(const float* __restrict__ b2,
                                                  float* __restrict__ out)
{
    extern __shared__ char sm[];
    int tid = threadIdx.x, lane = tid & 31, warp = tid >> 5;
    int wm = warp >> 1, wn = warp & 1;
    int grp = lane >> 2, thr = lane & 3;
    int g = blockIdx.z, b = g >> 4, e = g & 15;
    int m0 = blockIdx.y * 128, n0 = blockIdx.x * 128;

    const __half* arow = g_h + ((size_t)g * KCAP + m0 + (tid >> 1)) * DFFN;
    const __half* brow = g_w2t + (size_t)e * DD * DFFN
                         + (size_t)(n0 + (tid >> 1)) * DFFN;

    float acc[2][8][4] = {};
    gemm_mainloop(sm, arow, brow, tid, wm, wn, acc);

    const float* bias = b2 + e * DD + n0;
    float* outB = out + (size_t)b * SS * DD;
#pragma unroll
    for (int f = 0; f < 2; f++) {
        int mloc = wm * 32 + f * 16 + grp;
        int gi = g * KCAP + m0 + mloc;
        int tok0 = g_idx[gi], tok1 = g_idx[gi + 8];
        float gt0 = g_gate[gi], gt1 = g_gate[gi + 8];
        float* o0 = outB + (size_t)tok0 * DD + n0;
        float* o1 = outB + (size_t)tok1 * DD + n0;
#pragma unroll
        for (int j = 0; j < 8; j++) {
            int nloc = wn * 64 + j * 8 + thr * 2;
            float bv0 = bias[nloc], bv1 = bias[nloc + 1];
            atomicAdd(&o0[nloc],     (acc[f][j][0] + bv0) * gt0);
            atomicAdd(&o0[nloc + 1], (acc[f][j][1] + bv1) * gt0);
            atomicAdd(&o1[nloc],     (acc[f][j][2] + bv0) * gt1);
            atomicAdd(&o1[nloc + 1], (acc[f][j][3] + bv1) * gt1);
        }
    }
}

// ---------------------------------------------------------------------------
extern "C" void kernel_launch(void* const* d_in, const int* in_sizes, int n_in,
                              void* d_out, int out_size)
{
    const float* x  = (const float*)d_in[0];
    const float* gw = (const float*)d_in[1];
    const float* w1 = (const float*)d_in[2];
    const float* b1 = (const float*)d_in[3];
    const float* w2 = (const float*)d_in[4];
    const float* b2 = (const float*)d_in[5];
    float* out = (float*)d_out;

    cudaFuncSetAttribute(gemm1_h, cudaFuncAttributeMaxDynamicSharedMemorySize, SMEM_TOT);
    cudaFuncSetAttribute(gemm2_h, cudaFuncAttributeMaxDynamicSharedMemorySize, SMEM_TOT);

    dim3 trb(32, 8);
    // Launch order: profiler's launch-skip lands on gemm1 (4th launch).
    tr_w_kernel<<<dim3(16, 16, 2 * EE), trb>>>(w1, w2);
    router2_kernel<<<NTOK / 32, 256>>>((const float4*)x, gw);
    topk_kernel<<<NGRP, 1024>>>();

    gemm1_h<<<dim3(DFFN / 128, KCAP / 128, NGRP), 256, SMEM_TOT>>>(b1);

    int n4 = out_size / 4;
    zero_kernel<<<(n4 + 255) / 256, 256>>>((float4*)out, n4);

    gemm2_h<<<dim3(DD / 128, KCAP / 128, NGRP), 256, SMEM_TOT>>>(b2, out);
}

// round 17
// speedup vs baseline: 1.1067x; 1.0133x over previous
#include <cuda_runtime.h>
#include <cuda_fp16.h>
#include <math.h>
#include <stdint.h>

// Problem constants
#define BB   8
#define SS   8192
#define DD   512
#define EE   16
#define DFFN 512
#define KCAP 1024
#define NTOK (BB*SS)
#define NGRP (BB*EE)

// Scratch — referenced ONLY inside device code
__device__ float  g_aff [NGRP * SS];
__device__ int    g_idx [NGRP * KCAP];
__device__ float  g_gate[NGRP * KCAP];
__device__ __half g_h   [(size_t)NGRP * KCAP * DFFN];   // 128MB, fp16
__device__ __half g_xt  [(size_t)NTOK * DD];            // 64MB, x fp16
__device__ __half g_w1t [(size_t)EE * DFFN * DD];       // transposed [e][n][k]
__device__ __half g_w2t [(size_t)EE * DD * DFFN];       // transposed [e][n][k]

__device__ __forceinline__ void cpa16(uint32_t dst, const void* src)
{
    asm volatile("cp.async.cg.shared.global [%0], [%1], 16;\n" :: "r"(dst), "l"(src));
}
#define CP_COMMIT() asm volatile("cp.async.commit_group;\n" ::: "memory")
#define CP_WAIT0()  asm volatile("cp.async.wait_group 0;\n" ::: "memory")
#define CP_WAIT1()  asm volatile("cp.async.wait_group 1;\n" ::: "memory")

__device__ __forceinline__ uint32_t smem_u32(const void* p)
{
    uint32_t a;
    asm("{ .reg .u64 t; cvta.to.shared.u64 t, %1; cvt.u32.u64 %0, t; }" : "=r"(a) : "l"(p));
    return a;
}

// fp16 MMA: m16n8k16, row.col, fp32 accumulate
__device__ __forceinline__ void mma_f16(float* c, const unsigned* a,
                                        unsigned b0, unsigned b1)
{
    asm volatile(
        "mma.sync.aligned.m16n8k16.row.col.f32.f16.f16.f32 "
        "{%0,%1,%2,%3}, {%4,%5,%6,%7}, {%8,%9}, {%0,%1,%2,%3};\n"
        : "+f"(c[0]), "+f"(c[1]), "+f"(c[2]), "+f"(c[3])
        : "r"(a[0]), "r"(a[1]), "r"(a[2]), "r"(a[3]), "r"(b0), "r"(b1));
}

__device__ __forceinline__ void ldsm_x4(unsigned* r, uint32_t addr)
{
    asm volatile("ldmatrix.sync.aligned.m8n8.x4.shared.b16 {%0,%1,%2,%3}, [%4];"
                 : "=r"(r[0]), "=r"(r[1]), "=r"(r[2]), "=r"(r[3]) : "r"(addr));
}

// Fast exact-form tanh-gelu:  gelu(v) = v * e/(e+1),  e = exp(2*0.79788456*(v+0.044715 v^3))
// __expf (MUFU.EX2) + __fdividef (MUFU.RCP): ~1e-6 rel error, 4x fewer MUFU ops.
__device__ __forceinline__ float gelu_tanh(float v)
{
    float u2 = 1.5957691216057308f * (v + 0.044715f * v * v * v);
    float e = __expf(fminf(u2, 80.f));
    return v * __fdividef(e, e + 1.f);
}

// ---------------------------------------------------------------------------
// Merged weight transpose: z = which*16 + e  (DD == DFFN == 512)
// ---------------------------------------------------------------------------
__global__ void tr_w_kernel(const float* __restrict__ w1,
                            const float* __restrict__ w2)
{
    __shared__ float tile[32][33];
    int z = blockIdx.z;
    int e = z & 15, which = z >> 4;
    const float* S = (which ? w2 : w1) + (size_t)e * DD * DFFN;
    __half* Dp = (which ? g_w2t : g_w1t) + (size_t)e * DD * DFFN;
    int x = blockIdx.x * 32 + threadIdx.x;
#pragma unroll
    for (int r = 0; r < 4; r++) {
        int y = blockIdx.y * 32 + threadIdx.y + r * 8;
        tile[threadIdx.y + r * 8][threadIdx.x] = S[(size_t)y * 512 + x];
    }
    __syncthreads();
    int xo = blockIdx.y * 32 + threadIdx.x;
#pragma unroll
    for (int r = 0; r < 4; r++) {
        int yo = blockIdx.x * 32 + threadIdx.y + r * 8;
        Dp[(size_t)yo * 512 + xo] = __float2half_rn(tile[threadIdx.x][threadIdx.y + r * 8]);
    }
}

// ---------------------------------------------------------------------------
// Router — 4 tokens/warp, fused softmax + x->fp16
// ---------------------------------------------------------------------------
__global__ __launch_bounds__(256) void router2_kernel(
    const float4* __restrict__ x4, const float* __restrict__ gw)
{
    __shared__ float4 sgw4[EE][DD / 4];
    int tid = threadIdx.x;
    for (int i = tid; i < EE * (DD / 4); i += 256) {
        int e = i >> 7, dq = i & 127;
        float4 v;
        v.x = gw[(4 * dq + 0) * EE + e];
        v.y = gw[(4 * dq + 1) * EE + e];
        v.z = gw[(4 * dq + 2) * EE + e];
        v.w = gw[(4 * dq + 3) * EE + e];
        sgw4[e][dq] = v;
    }
    __syncthreads();

    int warp = tid >> 5, lane = tid & 31;
    int t0 = blockIdx.x * 32 + warp * 4;
    int b = t0 / SS;

    float acc[4][EE];
#pragma unroll
    for (int tt = 0; tt < 4; tt++)
#pragma unroll
        for (int e = 0; e < EE; e++) acc[tt][e] = 0.f;

#pragma unroll
    for (int q = 0; q < 4; q++) {
        int dq = lane + q * 32;
        float4 xv[4];
#pragma unroll
        for (int tt = 0; tt < 4; tt++)
            xv[tt] = x4[(size_t)(t0 + tt) * (DD / 4) + dq];
#pragma unroll
        for (int tt = 0; tt < 4; tt++) {
            __half2 h0 = __floats2half2_rn(xv[tt].x, xv[tt].y);
            __half2 h1 = __floats2half2_rn(xv[tt].z, xv[tt].w);
            uint2 pk; pk.x = *(unsigned*)&h0; pk.y = *(unsigned*)&h1;
            ((uint2*)g_xt)[(size_t)(t0 + tt) * (DD / 4) + dq] = pk;
        }
#pragma unroll
        for (int e = 0; e < EE; e++) {
            float4 w = sgw4[e][dq];
#pragma unroll
            for (int tt = 0; tt < 4; tt++) {
                acc[tt][e] = fmaf(xv[tt].x, w.x, acc[tt][e]);
                acc[tt][e] = fmaf(xv[tt].y, w.y, acc[tt][e]);
                acc[tt][e] = fmaf(xv[tt].z, w.z, acc[tt][e]);
                acc[tt][e] = fmaf(xv[tt].w, w.w, acc[tt][e]);
            }
        }
    }

#pragma unroll
    for (int tt = 0; tt < 4; tt++)
#pragma unroll
        for (int e = 0; e < EE; e++)
#pragma unroll
            for (int o = 16; o > 0; o >>= 1)
                acc[tt][e] += __shfl_xor_sync(0xffffffffu, acc[tt][e], o);

    int le = lane & 15;
#pragma unroll
    for (int tt = 0; tt < 4; tt++) {
        float m = acc[tt][0];
#pragma unroll
        for (int e = 1; e < EE; e++) m = fmaxf(m, acc[tt][e]);
        float v = expf(acc[tt][le] - m);
        float s = v;
#pragma unroll
        for (int o = 8; o > 0; o >>= 1)
            s += __shfl_xor_sync(0xffffffffu, s, o);
        if (lane < EE) {
            int srow = t0 + tt - b * SS;
            g_aff[((size_t)(b * EE + lane)) * SS + srow] = v * (1.f / s);
        }
    }
}

// ---------------------------------------------------------------------------
// Exact radix-select top-KCAP — 1024 threads/block
// ---------------------------------------------------------------------------
__global__ __launch_bounds__(1024) void topk_kernel()
{
    int g = blockIdx.x;
    const float* a = g_aff + (size_t)g * SS;
    int tid = threadIdx.x;

    __shared__ unsigned hist[256];
    __shared__ unsigned sPrefix, sMask, sRemain;

    if (tid == 0) { sPrefix = 0u; sMask = 0u; sRemain = KCAP; }
    __syncthreads();

    for (int pass = 3; pass >= 0; pass--) {
        if (tid < 256) hist[tid] = 0u;
        __syncthreads();
        unsigned pfx = sPrefix, msk = sMask;
        int sh = pass * 8;
        for (int s = tid; s < SS; s += 1024) {
            unsigned key = __float_as_uint(a[s]);
            if ((key & msk) == pfx)
                atomicAdd(&hist[(key >> sh) & 0xFFu], 1u);
        }
        __syncthreads();
        if (tid == 0) {
            unsigned need = sRemain, cum = 0;
            int d = 255;
            for (; d > 0; d--) {
                if (cum + hist[d] >= need) break;
                cum += hist[d];
            }
            sRemain = need - cum;
            sPrefix = pfx | ((unsigned)d << sh);
            sMask   = msk | (0xFFu << sh);
        }
        __syncthreads();
    }

    unsigned T = sPrefix;
    int kEq   = (int)sRemain;
    int cntGt = KCAP - kEq;

    __shared__ unsigned gtCnt;
    __shared__ int eqBase;
    __shared__ int warpEq[32];
    if (tid == 0) { gtCnt = 0u; eqBase = 0; }
    __syncthreads();

    int lane = tid & 31, warp = tid >> 5;
    int*   oIdx  = g_idx  + g * KCAP;
    float* oGate = g_gate + g * KCAP;

    for (int c = 0; c < SS / 1024; c++) {
        int s = c * 1024 + tid;
        float v = a[s];
        unsigned key = __float_as_uint(v);
        bool isGt = key > T, isEq = key == T;

        if (isGt) {
            unsigned p = atomicAdd(&gtCnt, 1u);
            oIdx[p] = s; oGate[p] = v;
        }
        unsigned bal = __ballot_sync(0xffffffffu, isEq);
        if (lane == 0) warpEq[warp] = __popc(bal);
        __syncthreads();
        if (isEq) {
            int r = eqBase;
#pragma unroll
            for (int w = 0; w < 32; w++) if (w < warp) r += warpEq[w];
            r += __popc(bal & ((1u << lane) - 1u));
            if (r < kEq) { oIdx[cntGt + r] = s; oGate[cntGt + r] = v; }
        }
        __syncthreads();
        if (tid == 0) {
            int tot = 0;
#pragma unroll
            for (int w = 0; w < 32; w++) tot += warpEq[w];
            eqBase += tot;
        }
        __syncthreads();
    }
}

// ---------------------------------------------------------------------------
// Zero output
// ---------------------------------------------------------------------------
__global__ void zero_kernel(float4* __restrict__ out, int n4)
{
    int i = blockIdx.x * blockDim.x + threadIdx.x;
    if (i < n4) out[i] = make_float4(0.f, 0.f, 0.f, 0.f);
}

// ---------------------------------------------------------------------------
// FP16 GEMM core: 256 threads (8 warps, 4m x 2n), CTA 128x128, warp 32x64.
// K chunk 32, 3-stage cp.async pipeline (prefetch distance 2), ldmatrix loads.
// Smem rows: 32 halves (64B) + 16B pad, stride 80B.
// ---------------------------------------------------------------------------
#define NSTG 16                    // 512 / 32
#define RSB 80                     // row stride bytes in smem
#define T_ST_B (128 * RSB)         // 10240 B per operand per stage
#define STG_B  (2 * T_ST_B)        // 20480 B per stage (A + B)
#define SMEM_TOT (3 * STG_B)       // 61440 B dynamic

// arow/brow point at this thread's row base (row = tid>>1); h=tid&1 covers 32B.
__device__ __forceinline__ void load_stage2(
    uint32_t sbase, const __half* arow, const __half* brow, int k0, int tid)
{
    int h = tid & 1;
    uint32_t da = sbase + (tid >> 1) * RSB + h * 32;
    const __half* ap = arow + k0 + h * 16;
    cpa16(da, ap);
    cpa16(da + 16, ap + 8);
    uint32_t db = sbase + T_ST_B + (tid >> 1) * RSB + h * 32;
    const __half* bp = brow + k0 + h * 16;
    cpa16(db, bp);
    cpa16(db + 16, bp + 8);
}

// One K16 sub-chunk: addresses already include stage+sub offsets.
__device__ __forceinline__ void compute_sub(
    uint32_t aA0, uint32_t aA1, uint32_t aB0, uint32_t aB1, uint32_t aB2,
    uint32_t aB3, float acc[2][8][4])
{
    unsigned a0[4], a1[4], b[16];
    ldsm_x4(a0, aA0);
    ldsm_x4(a1, aA1);
    ldsm_x4(&b[0], aB0);
    ldsm_x4(&b[4], aB1);
    ldsm_x4(&b[8], aB2);
    ldsm_x4(&b[12], aB3);
#pragma unroll
    for (int jp = 0; jp < 4; jp++) {
        mma_f16(acc[0][jp * 2],     a0, b[jp * 4],     b[jp * 4 + 1]);
        mma_f16(acc[1][jp * 2],     a1, b[jp * 4],     b[jp * 4 + 1]);
        mma_f16(acc[0][jp * 2 + 1], a0, b[jp * 4 + 2], b[jp * 4 + 3]);
        mma_f16(acc[1][jp * 2 + 1], a1, b[jp * 4 + 2], b[jp * 4 + 3]);
    }
}

__device__ __forceinline__ void gemm_mainloop(
    char* sm, const __half* arow, const __half* brow,
    int tid, int wm, int wn, float acc[2][8][4])
{
    uint32_t sb = smem_u32(sm);
    int lane = tid & 31;

    uint32_t aA[2], aB[4];
#pragma unroll
    for (int f = 0; f < 2; f++) {
        int row = wm * 32 + f * 16 + (lane & 7) + ((lane >> 3) & 1) * 8;
        aA[f] = sb + row * RSB + (lane >> 4) * 16;
    }
#pragma unroll
    for (int jp = 0; jp < 4; jp++) {
        int row = wn * 64 + jp * 16 + (lane & 7) + (lane >> 4) * 8;
        aB[jp] = sb + T_ST_B + row * RSB + ((lane >> 3) & 1) * 16;
    }

    // prefetch stages 0,1
#pragma unroll
    for (int s = 0; s < 2; s++) {
        load_stage2(sb + s * STG_B, arow, brow, s * 32, tid);
        CP_COMMIT();
    }

    for (int s = 0; s < NSTG; s++) {
        if (s < NSTG - 1) { CP_WAIT1(); } else { CP_WAIT0(); }
        __syncthreads();
        if (s + 2 < NSTG) {
            load_stage2(sb + ((s + 2) % 3) * STG_B, arow, brow, (s + 2) * 32, tid);
            CP_COMMIT();
        }
        uint32_t off = (s % 3) * STG_B;
        compute_sub(aA[0] + off, aA[1] + off, aB[0] + off, aB[1] + off,
                    aB[2] + off, aB[3] + off, acc);
        compute_sub(aA[0] + off + 32, aA[1] + off + 32, aB[0] + off + 32,
                    aB[1] + off + 32, aB[2] + off + 32, aB[3] + off + 32, acc);
        // no trailing barrier: next iteration's barrier orders buffer reuse
    }
}

// ---------------------------------------------------------------------------
// GEMM1: h = fp16(gelu(gather(x) @ w1 + b1))
// ---------------------------------------------------------------------------
__global__ __launch_bounds__(256, 2) void gemm1_h(const float* __restrict__ b1)
{
    extern __shared__ char sm[];
    int tid = threadIdx.x, lane = tid & 31, warp = tid >> 5;
    int wm = warp >> 1, wn = warp & 1;
    int grp = lane >> 2, thr = lane & 3;
    int g = blockIdx.z, b = g >> 4, e = g & 15;
    int m0 = blockIdx.y * 128, n0 = blockIdx.x * 128;

    int tok = g_idx[g * KCAP + m0 + (tid >> 1)];
    const __half* arow = g_xt + ((size_t)b * SS + tok) * DD;
    const __half* brow = g_w1t + (size_t)e * DFFN * DD
                         + (size_t)(n0 + (tid >> 1)) * DD;

    float acc[2][8][4] = {};
    gemm_mainloop(sm, arow, brow, tid, wm, wn, acc);

    const float* bias = b1 + e * DFFN + n0;
#pragma unroll
    for (int f = 0; f < 2; f++) {
        int mloc = wm * 32 + f * 16 + grp;
        __half* H0 = g_h + ((size_t)g * KCAP + m0 + mloc) * DFFN + n0;
        __half* H1 = H0 + 8 * DFFN;
#pragma unroll
        for (int j = 0; j < 8; j++) {
            int nloc = wn * 64 + j * 8 + thr * 2;
            float bv0 = bias[nloc], bv1 = bias[nloc + 1];
            __half2 v0 = __floats2half2_rn(gelu_tanh(acc[f][j][0] + bv0),
                                           gelu_tanh(acc[f][j][1] + bv1));
            *(__half2*)&H0[nloc] = v0;
            __half2 v1 = __floats2half2_rn(gelu_tanh(acc[f][j][2] + bv0),
                                           gelu_tanh(acc[f][j][3] + bv1));
            *(__half2*)&H1[nloc] = v1;
        }
    }
}

// ---------------------------------------------------------------------------
// GEMM2: out[tok] += gate * (h @ w2 + b2)
// ---------------------------------------------------------------------------
__global__ __launch_bounds__(256, 2) void gemm2_h(const float* __restrict__ b2,
                                                  float* __restrict__ out)
{
    extern __shared__ char sm[];
    int tid = threadIdx.x, lane = tid & 31, warp = tid >> 5;
    int wm = warp >> 1, wn = warp & 1;
    int grp = lane >> 2, thr = lane & 3;
    int g = blockIdx.z, b = g >> 4, e = g & 15;
    int m0 = blockIdx.y * 128, n0 = blockIdx.x * 128;

    const __half* arow = g_h + ((size_t)g * KCAP + m0 + (tid >> 1)) * DFFN;
    const __half* brow = g_w2t + (size_t)e * DD * DFFN
                         + (size_t)(n0 + (tid >> 1)) * DFFN;

    float acc[2][8][4] = {};
    gemm_mainloop(sm, arow, brow, tid, wm, wn, acc);

    const float* bias = b2 + e * DD + n0;
    float* outB = out + (size_t)b * SS * DD;
#pragma unroll
    for (int f = 0; f < 2; f++) {
        int mloc = wm * 32 + f * 16 + grp;
        int gi = g * KCAP + m0 + mloc;
        int tok0 = g_idx[gi], tok1 = g_idx[gi + 8];
        float gt0 = g_gate[gi], gt1 = g_gate[gi + 8];
        float* o0 = outB + (size_t)tok0 * DD + n0;
        float* o1 = outB + (size_t)tok1 * DD + n0;
#pragma unroll
        for (int j = 0; j < 8; j++) {
            int nloc = wn * 64 + j * 8 + thr * 2;
            float bv0 = bias[nloc], bv1 = bias[nloc + 1];
            atomicAdd(&o0[nloc],     (acc[f][j][0] + bv0) * gt0);
            atomicAdd(&o0[nloc + 1], (acc[f][j][1] + bv1) * gt0);
            atomicAdd(&o1[nloc],     (acc[f][j][2] + bv0) * gt1);
            atomicAdd(&o1[nloc + 1], (acc[f][j][3] + bv1) * gt1);
        }
    }
}

// ---------------------------------------------------------------------------
extern "C" void kernel_launch(void* const* d_in, const int* in_sizes, int n_in,
                              void* d_out, int out_size)
{
    const float* x  = (const float*)d_in[0];
    const float* gw = (const float*)d_in[1];
    const float* w1 = (const float*)d_in[2];
    const float* b1 = (const float*)d_in[3];
    const float* w2 = (const float*)d_in[4];
    const float* b2 = (const float*)d_in[5];
    float* out = (float*)d_out;

    cudaFuncSetAttribute(gemm1_h, cudaFuncAttributeMaxDynamicSharedMemorySize, SMEM_TOT);
    cudaFuncSetAttribute(gemm2_h, cudaFuncAttributeMaxDynamicSharedMemorySize, SMEM_TOT);

    dim3 trb(32, 8);
    // Launch order: profiler's launch-skip lands on gemm1 (4th launch).
    tr_w_kernel<<<dim3(16, 16, 2 * EE), trb>>>(w1, w2);
    router2_kernel<<<NTOK / 32, 256>>>((const float4*)x, gw);
    topk_kernel<<<NGRP, 1024>>>();

    gemm1_h<<<dim3(DFFN / 128, KCAP / 128, NGRP), 256, SMEM_TOT>>>(b1);

    int n4 = out_size / 4;
    zero_kernel<<<(n4 + 255) / 256, 256>>>((float4*)out, n4);

    gemm2_h<<<dim3(DD / 128, KCAP / 128, NGRP), 256, SMEM_TOT>>>(b2, out);
}